// round 15
// baseline (speedup 1.0000x reference)
#include <cuda_runtime.h>
#include <cuda_fp16.h>
#include <math.h>
#include <stdint.h>

#define T_TOK 8192
#define D_DIM 1024
#define H_DIM 4096
#define E_NUM 8

// ---------------- static device scratch ----------------
__device__ int    g_cnt[E_NUM];
__device__ float  g_imp[E_NUM];
__device__ float  g_ent;
__device__ int    g_tok[E_NUM * T_TOK];
__device__ float  g_wt [E_NUM * T_TOK];
__device__ __half g_xh [8388608];       // fp16 x [T][D] (16 MB)
__device__ __half g_hidh[268435456];    // [E*T][H] hidden fp16 (512 MB)
__device__ __half g_wth[100663296];     // transposed fp16 weights (192 MB)
#define WGT_OFF 0
#define WUT_OFF 33554432
#define WDT_OFF 67108864

// ---------------- helpers ----------------
__device__ __forceinline__ uint32_t smem_u32(const void* p) {
    uint32_t a;
    asm("{ .reg .u64 t; cvta.to.shared.u64 t, %1; cvt.u32.u64 %0, t; }" : "=r"(a) : "l"(p));
    return a;
}
#define MMA_F16(c, a, b) \
    asm volatile("mma.sync.aligned.m16n8k16.row.col.f32.f16.f16.f32 " \
        "{%0,%1,%2,%3}, {%4,%5,%6,%7}, {%8,%9}, {%0,%1,%2,%3};" \
        : "+f"((c)[0]), "+f"((c)[1]), "+f"((c)[2]), "+f"((c)[3]) \
        : "r"((a)[0]), "r"((a)[1]), "r"((a)[2]), "r"((a)[3]), "r"((b)[0]), "r"((b)[1]))
#define LDM4(r0, r1, r2, r3, addr) \
    asm volatile("ldmatrix.sync.aligned.m8n8.x4.shared.b16 {%0,%1,%2,%3}, [%4];" \
        : "=r"(r0), "=r"(r1), "=r"(r2), "=r"(r3) : "r"(addr))
#define CP16(s, g) asm volatile("cp.async.cg.shared.global [%0], [%1], 16;" :: "r"(s), "l"(g) : "memory")
#define CP_COMMIT() asm volatile("cp.async.commit_group;" ::: "memory")

// ---- SMEM tiles: 128 rows x 72 halves (144 B pitch), K-chunk = 64 halves ----
#define ABUF1  0          // 2 x 18432
#define BGBUF  36864
#define BUBUF  73728
#define TOKO1  110592
#define SMEM1  111104
#define ABUF2  0
#define BBUF2  36864
#define TOKO2  73728
#define WTO2   74240
#define SMEM2  74752

// ---------------- reset per launch ----------------
__global__ void zero_kernel() {
    int i = threadIdx.x;
    if (i < E_NUM) { g_cnt[i] = 0; g_imp[i] = 0.f; }
    if (i == 0) g_ent = 0.f;
}

// ---------------- fp16-convert x ----------------
__global__ void round_x_kernel(const float* __restrict__ x) {
    int i = blockIdx.x * 256 + threadIdx.x;
    float4 v = ((const float4*)x)[i];
    ((__half2*)g_xh)[2 * i]     = __floats2half2_rn(v.x, v.y);
    ((__half2*)g_xh)[2 * i + 1] = __floats2half2_rn(v.z, v.w);
}

// ---------------- weight transpose + fp16: src [e][R][C] -> dst [e][C][R] ----------------
__global__ void transpose_kernel(const float* __restrict__ src, int dst_off, int R, int C) {
    __shared__ float t[32][33];
    int e = blockIdx.z;
    const float* s = src + (size_t)e * R * C;
    __half* d = g_wth + dst_off + (size_t)e * R * C;
    int c0 = blockIdx.x * 32, r0 = blockIdx.y * 32;
    int lx = threadIdx.x, ly = threadIdx.y;
    #pragma unroll
    for (int i = 0; i < 32; i += 8)
        t[ly + i][lx] = s[(size_t)(r0 + ly + i) * C + c0 + lx];
    __syncthreads();
    #pragma unroll
    for (int i = 0; i < 32; i += 8)
        d[(size_t)(c0 + ly + i) * R + r0 + lx] = __float2half_rn(t[lx][ly + i]);
}

// ---------------- router: 1 warp per token ----------------
__global__ void router_kernel(const float* __restrict__ x,
                              const float* __restrict__ rw,
                              const float* __restrict__ temp) {
    int warp = (blockIdx.x * blockDim.x + threadIdx.x) >> 5;
    int lane = threadIdx.x & 31;
    if (warp >= T_TOK) return;
    int t = warp;
    float p[8] = {0,0,0,0,0,0,0,0};
    const float* xr = x + (size_t)t * D_DIM;
    for (int d = lane; d < D_DIM; d += 32) {
        float xv = xr[d];
        float4 w0 = *(const float4*)(rw + d * 8);
        float4 w1 = *(const float4*)(rw + d * 8 + 4);
        p[0] += xv * w0.x; p[1] += xv * w0.y; p[2] += xv * w0.z; p[3] += xv * w0.w;
        p[4] += xv * w1.x; p[5] += xv * w1.y; p[6] += xv * w1.z; p[7] += xv * w1.w;
    }
    #pragma unroll
    for (int off = 16; off; off >>= 1)
        #pragma unroll
        for (int e = 0; e < 8; e++) p[e] += __shfl_down_sync(0xffffffffu, p[e], off);

    if (lane == 0) {
        float tt = fminf(fmaxf(temp[0], 0.1f), 5.0f);
        float mx = -1e30f;
        #pragma unroll
        for (int e = 0; e < 8; e++) { p[e] /= tt; mx = fmaxf(mx, p[e]); }
        float s = 0.f;
        #pragma unroll
        for (int e = 0; e < 8; e++) { p[e] = expf(p[e] - mx); s += p[e]; }
        float inv = 1.0f / s;
        float ent = 0.f;
        #pragma unroll
        for (int e = 0; e < 8; e++) {
            p[e] *= inv;
            ent -= p[e] * logf(fmaxf(p[e], 1e-8f));
            atomicAdd(&g_imp[e], p[e]);
        }
        atomicAdd(&g_ent, ent);
        int i1 = 0; float v1 = p[0];
        #pragma unroll
        for (int e = 1; e < 8; e++) if (p[e] > v1) { v1 = p[e]; i1 = e; }
        int i2 = -1; float v2 = -1.0f;
        #pragma unroll
        for (int e = 0; e < 8; e++) if (e != i1 && p[e] > v2) { v2 = p[e]; i2 = e; }
        int p1 = atomicAdd(&g_cnt[i1], 1);
        g_tok[i1 * T_TOK + p1] = t; g_wt[i1 * T_TOK + p1] = v1;
        int p2 = atomicAdd(&g_cnt[i2], 1);
        g_tok[i2 * T_TOK + p2] = t; g_wt[i2 * T_TOK + p2] = v2;
    }
}

// ---------------- stage A fused: gate & up fp16 GEMM + SwiGLU epilogue ----------------
__global__ void __launch_bounds__(256, 1) ffn1_kernel() {
    int e = blockIdx.z;
    int ne = g_cnt[e];
    int m0 = blockIdx.x * 128;
    if (m0 >= ne) return;
    int n0 = blockIdx.y * 128;
    extern __shared__ char smem[];
    uint32_t sbase = smem_u32(smem);
    int tid = threadIdx.x, warp = tid >> 5, lane = tid & 31;
    int wm = warp >> 2, wn = warp & 3;
    int ar = lane >> 2, ac = lane & 3;
    int* toks = (int*)(smem + TOKO1);

    if (tid < 128) toks[tid] = (m0 + tid < ne) ? g_tok[e * T_TOK + m0 + tid] : 0;
    __syncthreads();

    const __half* ag[4]; const __half *bgg[4], *bgu[4]; uint32_t aso[4];
    #pragma unroll
    for (int j = 0; j < 4; j++) {
        int f = tid + 256 * j, row = f >> 3, c4 = f & 7;
        ag[j]  = g_xh + (size_t)toks[row] * D_DIM + c4 * 8;
        size_t boff = (size_t)(e * H_DIM + n0 + row) * D_DIM + c4 * 8;
        bgg[j] = g_wth + WGT_OFF + boff;
        bgu[j] = g_wth + WUT_OFF + boff;
        aso[j] = row * 144 + c4 * 16;
    }

    auto load_tile = [&](int kc, int buf) {
        uint32_t sa = sbase + ABUF1 + buf * 18432;
        uint32_t sg = sbase + BGBUF + buf * 18432;
        uint32_t su = sbase + BUBUF + buf * 18432;
        int ko = kc * 64;
        #pragma unroll
        for (int j = 0; j < 4; j++) {
            CP16(sa + aso[j], ag[j] + ko);
            CP16(sg + aso[j], bgg[j] + ko);
            CP16(su + aso[j], bgu[j] + ko);
        }
        CP_COMMIT();
    };

    // ldmatrix lane-address offsets (within a tile buffer)
    uint32_t lsel = (lane >> 4) * 16;           // 0 or 16 B (k 0-7 vs 8-15)
    uint32_t lrow = lane & 15;
    uint32_t amo[4], bno[2];
    #pragma unroll
    for (int mf = 0; mf < 4; mf++) amo[mf] = (wm * 64 + mf * 16 + lrow) * 144 + lsel;
    #pragma unroll
    for (int np = 0; np < 2; np++) bno[np] = (wn * 32 + np * 16 + lrow) * 144 + lsel;

    float accg[4][4][4], accu[4][4][4];
    #pragma unroll
    for (int i = 0; i < 4; i++)
        #pragma unroll
        for (int j = 0; j < 4; j++)
            #pragma unroll
            for (int k = 0; k < 4; k++) { accg[i][j][k] = 0.f; accu[i][j][k] = 0.f; }

    load_tile(0, 0);
    const int KT = D_DIM / 64;
    for (int kc = 0; kc < KT; kc++) {
        int cur = kc & 1;
        if (kc + 1 < KT) {
            load_tile(kc + 1, cur ^ 1);
            asm volatile("cp.async.wait_group 1;" ::: "memory");
        } else {
            asm volatile("cp.async.wait_group 0;" ::: "memory");
        }
        __syncthreads();
        uint32_t sa = sbase + ABUF1 + cur * 18432;
        uint32_t sg = sbase + BGBUF + cur * 18432;
        uint32_t su = sbase + BUBUF + cur * 18432;
        #pragma unroll
        for (int ks = 0; ks < 4; ks++) {
            uint32_t af[4][4], bg[4][2], bu[4][2];
            #pragma unroll
            for (int mf = 0; mf < 4; mf++)
                LDM4(af[mf][0], af[mf][1], af[mf][2], af[mf][3], sa + amo[mf] + ks * 32);
            #pragma unroll
            for (int np = 0; np < 2; np++) {
                uint32_t r0, r1, r2, r3;
                LDM4(r0, r1, r2, r3, sg + bno[np] + ks * 32);
                bg[2 * np][0] = r0; bg[2 * np][1] = r2;
                bg[2 * np + 1][0] = r1; bg[2 * np + 1][1] = r3;
                LDM4(r0, r1, r2, r3, su + bno[np] + ks * 32);
                bu[2 * np][0] = r0; bu[2 * np][1] = r2;
                bu[2 * np + 1][0] = r1; bu[2 * np + 1][1] = r3;
            }
            #pragma unroll
            for (int mf = 0; mf < 4; mf++)
                #pragma unroll
                for (int nf = 0; nf < 4; nf++) {
                    MMA_F16(accg[mf][nf], af[mf], bg[nf]);
                    MMA_F16(accu[mf][nf], af[mf], bu[nf]);
                }
        }
        __syncthreads();
    }

    // epilogue: hidden = fp16(gate * silu(up))
    #pragma unroll
    for (int mf = 0; mf < 4; mf++) {
        int mrow = wm * 64 + mf * 16 + ar;
        #pragma unroll
        for (int nf = 0; nf < 4; nf++) {
            int ncol = n0 + wn * 32 + nf * 8 + 2 * ac;
            if (m0 + mrow < ne) {
                float u0 = accu[mf][nf][0], u1 = accu[mf][nf][1];
                float h0 = accg[mf][nf][0] * (u0 / (1.f + __expf(-u0)));
                float h1 = accg[mf][nf][1] * (u1 / (1.f + __expf(-u1)));
                *(__half2*)(g_hidh + (size_t)(e * T_TOK + m0 + mrow) * H_DIM + ncol) = __floats2half2_rn(h0, h1);
            }
            if (m0 + mrow + 8 < ne) {
                float u2 = accu[mf][nf][2], u3 = accu[mf][nf][3];
                float h2 = accg[mf][nf][2] * (u2 / (1.f + __expf(-u2)));
                float h3 = accg[mf][nf][3] * (u3 / (1.f + __expf(-u3)));
                *(__half2*)(g_hidh + (size_t)(e * T_TOK + m0 + mrow + 8) * H_DIM + ncol) = __floats2half2_rn(h2, h3);
            }
        }
    }
}

// ---------------- stage B: out[tok[m],:] += w[m] * (hidden[m,:] @ Wd^T[e][n,:]) ----------------
__global__ void __launch_bounds__(256, 2) ffn2_kernel(float* __restrict__ out) {
    int e = blockIdx.z;
    int ne = g_cnt[e];
    int m0 = blockIdx.x * 128;
    if (m0 >= ne) return;
    int n0 = blockIdx.y * 128;
    extern __shared__ char smem[];
    uint32_t sbase = smem_u32(smem);
    int tid = threadIdx.x, warp = tid >> 5, lane = tid & 31;
    int wm = warp >> 2, wn = warp & 3;
    int ar = lane >> 2, ac = lane & 3;
    int*   toks = (int*)(smem + TOKO2);
    float* wts  = (float*)(smem + WTO2);

    if (tid < 128) {
        int valid = (m0 + tid < ne);
        toks[tid] = valid ? g_tok[e * T_TOK + m0 + tid] : 0;
        wts[tid]  = valid ? g_wt [e * T_TOK + m0 + tid] : 0.f;
    }
    __syncthreads();

    const __half* ag[4]; const __half* bg[4]; uint32_t aso[4];
    #pragma unroll
    for (int j = 0; j < 4; j++) {
        int f = tid + 256 * j, row = f >> 3, c4 = f & 7;
        ag[j] = g_hidh + (size_t)(e * T_TOK + m0 + row) * H_DIM + c4 * 8;
        bg[j] = g_wth + WDT_OFF + (size_t)(e * D_DIM + n0 + row) * H_DIM + c4 * 8;
        aso[j] = row * 144 + c4 * 16;
    }

    auto load_tile = [&](int kc, int buf) {
        uint32_t sa = sbase + ABUF2 + buf * 18432;
        uint32_t sb = sbase + BBUF2 + buf * 18432;
        int ko = kc * 64;
        #pragma unroll
        for (int j = 0; j < 4; j++) {
            CP16(sa + aso[j], ag[j] + ko);
            CP16(sb + aso[j], bg[j] + ko);
        }
        CP_COMMIT();
    };

    uint32_t lsel = (lane >> 4) * 16;
    uint32_t lrow = lane & 15;
    uint32_t amo[4], bno[2];
    #pragma unroll
    for (int mf = 0; mf < 4; mf++) amo[mf] = (wm * 64 + mf * 16 + lrow) * 144 + lsel;
    #pragma unroll
    for (int np = 0; np < 2; np++) bno[np] = (wn * 32 + np * 16 + lrow) * 144 + lsel;

    float acc[4][4][4];
    #pragma unroll
    for (int i = 0; i < 4; i++)
        #pragma unroll
        for (int j = 0; j < 4; j++)
            #pragma unroll
            for (int k = 0; k < 4; k++) acc[i][j][k] = 0.f;

    load_tile(0, 0);
    const int KT = H_DIM / 64;
    for (int kc = 0; kc < KT; kc++) {
        int cur = kc & 1;
        if (kc + 1 < KT) {
            load_tile(kc + 1, cur ^ 1);
            asm volatile("cp.async.wait_group 1;" ::: "memory");
        } else {
            asm volatile("cp.async.wait_group 0;" ::: "memory");
        }
        __syncthreads();
        uint32_t sa = sbase + ABUF2 + cur * 18432;
        uint32_t sb = sbase + BBUF2 + cur * 18432;
        #pragma unroll
        for (int ks = 0; ks < 4; ks++) {
            uint32_t af[4][4], bf[4][2];
            #pragma unroll
            for (int mf = 0; mf < 4; mf++)
                LDM4(af[mf][0], af[mf][1], af[mf][2], af[mf][3], sa + amo[mf] + ks * 32);
            #pragma unroll
            for (int np = 0; np < 2; np++) {
                uint32_t r0, r1, r2, r3;
                LDM4(r0, r1, r2, r3, sb + bno[np] + ks * 32);
                bf[2 * np][0] = r0; bf[2 * np][1] = r2;
                bf[2 * np + 1][0] = r1; bf[2 * np + 1][1] = r3;
            }
            #pragma unroll
            for (int mf = 0; mf < 4; mf++)
                #pragma unroll
                for (int nf = 0; nf < 4; nf++)
                    MMA_F16(acc[mf][nf], af[mf], bf[nf]);
        }
        __syncthreads();
    }

    #pragma unroll
    for (int mf = 0; mf < 4; mf++) {
        int mrow = wm * 64 + mf * 16 + ar;
        #pragma unroll
        for (int nf = 0; nf < 4; nf++) {
            int ncol = n0 + wn * 32 + nf * 8 + 2 * ac;
            if (m0 + mrow < ne) {
                float w = wts[mrow];
                float* dst = out + (size_t)toks[mrow] * D_DIM + ncol;
                atomicAdd(dst,     w * acc[mf][nf][0]);
                atomicAdd(dst + 1, w * acc[mf][nf][1]);
            }
            if (m0 + mrow + 8 < ne) {
                float w = wts[mrow + 8];
                float* dst = out + (size_t)toks[mrow + 8] * D_DIM + ncol;
                atomicAdd(dst,     w * acc[mf][nf][2]);
                atomicAdd(dst + 1, w * acc[mf][nf][3]);
            }
        }
    }
}

// ---------------- aux scalars ----------------
__global__ void finalize_kernel(float* out, int out_size) {
    float aux = 0.f;
    for (int e = 0; e < E_NUM; e++) {
        float imp  = g_imp[e] / 8192.0f;
        float load = (float)g_cnt[e] / (8192.0f + 1e-6f);
        aux += imp * load;
    }
    aux *= (float)E_NUM * 0.01f;
    float ent = g_ent / 8192.0f * 0.01f;
    out[out_size - 3] = aux;
    out[out_size - 2] = ent;
    out[out_size - 1] = 0.f;
}

// ---------------- launch ----------------
extern "C" void kernel_launch(void* const* d_in, const int* in_sizes, int n_in,
                              void* d_out, int out_size) {
    const float* x    = (const float*)d_in[0];
    const float* rw   = (const float*)d_in[1];
    const float* temp = (const float*)d_in[2];
    const float* Wg   = (const float*)d_in[3];
    const float* Wu   = (const float*)d_in[4];
    const float* Wd   = (const float*)d_in[5];
    float* out = (float*)d_out;

    cudaFuncSetAttribute(ffn1_kernel, cudaFuncAttributeMaxDynamicSharedMemorySize, SMEM1);
    cudaFuncSetAttribute(ffn2_kernel, cudaFuncAttributeMaxDynamicSharedMemorySize, SMEM2);

    cudaMemsetAsync(d_out, 0, (size_t)out_size * sizeof(float));
    zero_kernel<<<1, 32>>>();

    round_x_kernel<<<8192, 256>>>(x);
    dim3 tb(32, 8);
    transpose_kernel<<<dim3(H_DIM / 32, D_DIM / 32, E_NUM), tb>>>(Wg, WGT_OFF, D_DIM, H_DIM);
    transpose_kernel<<<dim3(H_DIM / 32, D_DIM / 32, E_NUM), tb>>>(Wu, WUT_OFF, D_DIM, H_DIM);
    transpose_kernel<<<dim3(D_DIM / 32, H_DIM / 32, E_NUM), tb>>>(Wd, WDT_OFF, H_DIM, D_DIM);

    router_kernel<<<T_TOK / 8, 256>>>(x, rw, temp);

    ffn1_kernel<<<dim3(64, H_DIM / 128, E_NUM), 256, SMEM1>>>();
    ffn2_kernel<<<dim3(64, D_DIM / 128, E_NUM), 256, SMEM2>>>(out);

    finalize_kernel<<<1, 1>>>(out, out_size);
}

// round 16
// speedup vs baseline: 1.0584x; 1.0584x over previous
#include <cuda_runtime.h>
#include <cuda_fp16.h>
#include <math.h>
#include <stdint.h>

#define T_TOK 8192
#define D_DIM 1024
#define H_DIM 4096
#define E_NUM 8

// ---------------- static device scratch ----------------
__device__ int    g_cnt[E_NUM];
__device__ float  g_imp[E_NUM];
__device__ float  g_ent;
__device__ int    g_tok[E_NUM * T_TOK];
__device__ float  g_wt [E_NUM * T_TOK];
__device__ __half g_xh [8388608];       // fp16 x [T][D] (16 MB)
__device__ __half g_hidh[268435456];    // [E*T][H] hidden fp16 (512 MB)
__device__ __half g_wth[100663296];     // transposed fp16 weights (192 MB)
#define WGT_OFF 0
#define WUT_OFF 33554432
#define WDT_OFF 67108864

// ---------------- helpers ----------------
__device__ __forceinline__ uint32_t smem_u32(const void* p) {
    uint32_t a;
    asm("{ .reg .u64 t; cvta.to.shared.u64 t, %1; cvt.u32.u64 %0, t; }" : "=r"(a) : "l"(p));
    return a;
}
#define MMA_F16(c, a, b) \
    asm volatile("mma.sync.aligned.m16n8k16.row.col.f32.f16.f16.f32 " \
        "{%0,%1,%2,%3}, {%4,%5,%6,%7}, {%8,%9}, {%0,%1,%2,%3};" \
        : "+f"((c)[0]), "+f"((c)[1]), "+f"((c)[2]), "+f"((c)[3]) \
        : "r"((a)[0]), "r"((a)[1]), "r"((a)[2]), "r"((a)[3]), "r"((b)[0]), "r"((b)[1]))
#define CP16(s, g) asm volatile("cp.async.cg.shared.global [%0], [%1], 16;" :: "r"(s), "l"(g) : "memory")
#define CP_COMMIT() asm volatile("cp.async.commit_group;" ::: "memory")

// ---- SMEM tiles: 128 rows x 72 halves (144 B pitch = 36 words), K-chunk = 64 ----
#define ABUF1  0          // 2 x 18432
#define BGBUF  36864
#define BUBUF  73728
#define TOKO1  110592
#define SMEM1  111104
#define ABUF2  0
#define BBUF2  36864
#define TOKO2  73728
#define WTO2   74240
#define SMEM2  74752

// ---------------- reset per launch ----------------
__global__ void zero_kernel() {
    int i = threadIdx.x;
    if (i < E_NUM) { g_cnt[i] = 0; g_imp[i] = 0.f; }
    if (i == 0) g_ent = 0.f;
}

// ---------------- weight transpose + fp16: src [e][R][C] -> dst [e][C][R] ----------------
__global__ void transpose_kernel(const float* __restrict__ src, int dst_off, int R, int C) {
    __shared__ float t[32][33];
    int e = blockIdx.z;
    const float* s = src + (size_t)e * R * C;
    __half* d = g_wth + dst_off + (size_t)e * R * C;
    int c0 = blockIdx.x * 32, r0 = blockIdx.y * 32;
    int lx = threadIdx.x, ly = threadIdx.y;
    #pragma unroll
    for (int i = 0; i < 32; i += 8)
        t[ly + i][lx] = s[(size_t)(r0 + ly + i) * C + c0 + lx];
    __syncthreads();
    #pragma unroll
    for (int i = 0; i < 32; i += 8)
        d[(size_t)(c0 + ly + i) * R + r0 + lx] = __float2half_rn(t[lx][ly + i]);
}

// ---------------- router: 1 warp per token; also converts x -> fp16 ----------------
__global__ void router_kernel(const float* __restrict__ x,
                              const float* __restrict__ rw,
                              const float* __restrict__ temp) {
    int warp = (blockIdx.x * blockDim.x + threadIdx.x) >> 5;
    int lane = threadIdx.x & 31;
    if (warp >= T_TOK) return;
    int t = warp;
    float p[8] = {0,0,0,0,0,0,0,0};
    const float* xr = x + (size_t)t * D_DIM;
    __half* xh = g_xh + (size_t)t * D_DIM;
    for (int d = lane; d < D_DIM; d += 32) {
        float xv = xr[d];
        xh[d] = __float2half_rn(xv);
        float4 w0 = *(const float4*)(rw + d * 8);
        float4 w1 = *(const float4*)(rw + d * 8 + 4);
        p[0] += xv * w0.x; p[1] += xv * w0.y; p[2] += xv * w0.z; p[3] += xv * w0.w;
        p[4] += xv * w1.x; p[5] += xv * w1.y; p[6] += xv * w1.z; p[7] += xv * w1.w;
    }
    #pragma unroll
    for (int off = 16; off; off >>= 1)
        #pragma unroll
        for (int e = 0; e < 8; e++) p[e] += __shfl_down_sync(0xffffffffu, p[e], off);

    if (lane == 0) {
        float tt = fminf(fmaxf(temp[0], 0.1f), 5.0f);
        float mx = -1e30f;
        #pragma unroll
        for (int e = 0; e < 8; e++) { p[e] /= tt; mx = fmaxf(mx, p[e]); }
        float s = 0.f;
        #pragma unroll
        for (int e = 0; e < 8; e++) { p[e] = expf(p[e] - mx); s += p[e]; }
        float inv = 1.0f / s;
        float ent = 0.f;
        #pragma unroll
        for (int e = 0; e < 8; e++) {
            p[e] *= inv;
            ent -= p[e] * logf(fmaxf(p[e], 1e-8f));
            atomicAdd(&g_imp[e], p[e]);
        }
        atomicAdd(&g_ent, ent);
        int i1 = 0; float v1 = p[0];
        #pragma unroll
        for (int e = 1; e < 8; e++) if (p[e] > v1) { v1 = p[e]; i1 = e; }
        int i2 = -1; float v2 = -1.0f;
        #pragma unroll
        for (int e = 0; e < 8; e++) if (e != i1 && p[e] > v2) { v2 = p[e]; i2 = e; }
        int p1 = atomicAdd(&g_cnt[i1], 1);
        g_tok[i1 * T_TOK + p1] = t; g_wt[i1 * T_TOK + p1] = v1;
        int p2 = atomicAdd(&g_cnt[i2], 1);
        g_tok[i2 * T_TOK + p2] = t; g_wt[i2 * T_TOK + p2] = v2;
    }
}

// ---------------- stage A fused: gate & up fp16 GEMM + SwiGLU epilogue (R14-proven) ----------------
__global__ void __launch_bounds__(256, 1) ffn1_kernel() {
    int e = blockIdx.z;
    int ne = g_cnt[e];
    int m0 = blockIdx.x * 128;
    if (m0 >= ne) return;
    int n0 = blockIdx.y * 128;
    extern __shared__ char smem[];
    uint32_t sbase = smem_u32(smem);
    int tid = threadIdx.x, warp = tid >> 5, lane = tid & 31;
    int wm = warp >> 2, wn = warp & 3;
    int ar = lane >> 2, ac = lane & 3;
    int* toks = (int*)(smem + TOKO1);

    if (tid < 128) toks[tid] = (m0 + tid < ne) ? g_tok[e * T_TOK + m0 + tid] : 0;
    __syncthreads();

    const __half* ag[4]; const __half *bgg[4], *bgu[4]; uint32_t aso[4];
    #pragma unroll
    for (int j = 0; j < 4; j++) {
        int f = tid + 256 * j, row = f >> 3, c4 = f & 7;
        ag[j]  = g_xh + (size_t)toks[row] * D_DIM + c4 * 8;
        size_t boff = (size_t)(e * H_DIM + n0 + row) * D_DIM + c4 * 8;
        bgg[j] = g_wth + WGT_OFF + boff;
        bgu[j] = g_wth + WUT_OFF + boff;
        aso[j] = row * 144 + c4 * 16;
    }

    auto load_tile = [&](int kc, int buf) {
        uint32_t sa = sbase + ABUF1 + buf * 18432;
        uint32_t sg = sbase + BGBUF + buf * 18432;
        uint32_t su = sbase + BUBUF + buf * 18432;
        int ko = kc * 64;
        #pragma unroll
        for (int j = 0; j < 4; j++) {
            CP16(sa + aso[j], ag[j] + ko);
            CP16(sg + aso[j], bgg[j] + ko);
            CP16(su + aso[j], bgu[j] + ko);
        }
        CP_COMMIT();
    };

    float accg[4][4][4], accu[4][4][4];
    #pragma unroll
    for (int i = 0; i < 4; i++)
        #pragma unroll
        for (int j = 0; j < 4; j++)
            #pragma unroll
            for (int k = 0; k < 4; k++) { accg[i][j][k] = 0.f; accu[i][j][k] = 0.f; }

    load_tile(0, 0);
    const int KT = D_DIM / 64;
    for (int kc = 0; kc < KT; kc++) {
        int cur = kc & 1;
        if (kc + 1 < KT) {
            load_tile(kc + 1, cur ^ 1);
            asm volatile("cp.async.wait_group 1;" ::: "memory");
        } else {
            asm volatile("cp.async.wait_group 0;" ::: "memory");
        }
        __syncthreads();
        const uint32_t* A32 = (const uint32_t*)(smem + ABUF1 + cur * 18432);
        const uint32_t* G32 = (const uint32_t*)(smem + BGBUF + cur * 18432);
        const uint32_t* U32 = (const uint32_t*)(smem + BUBUF + cur * 18432);
        #pragma unroll
        for (int ks = 0; ks < 4; ks++) {
            uint32_t af[4][4], bg[4][2], bu[4][2];
            #pragma unroll
            for (int mf = 0; mf < 4; mf++) {
                int base = (wm * 64 + mf * 16 + ar) * 36 + ks * 8 + ac;
                af[mf][0] = A32[base];       af[mf][1] = A32[base + 288];
                af[mf][2] = A32[base + 4];   af[mf][3] = A32[base + 292];
            }
            #pragma unroll
            for (int nf = 0; nf < 4; nf++) {
                int base = (wn * 32 + nf * 8 + ar) * 36 + ks * 8 + ac;
                bg[nf][0] = G32[base]; bg[nf][1] = G32[base + 4];
                bu[nf][0] = U32[base]; bu[nf][1] = U32[base + 4];
            }
            #pragma unroll
            for (int mf = 0; mf < 4; mf++)
                #pragma unroll
                for (int nf = 0; nf < 4; nf++) {
                    MMA_F16(accg[mf][nf], af[mf], bg[nf]);
                    MMA_F16(accu[mf][nf], af[mf], bu[nf]);
                }
        }
        __syncthreads();
    }

    // epilogue: hidden = fp16(gate * silu(up))
    #pragma unroll
    for (int mf = 0; mf < 4; mf++) {
        int mrow = wm * 64 + mf * 16 + ar;
        #pragma unroll
        for (int nf = 0; nf < 4; nf++) {
            int ncol = n0 + wn * 32 + nf * 8 + 2 * ac;
            if (m0 + mrow < ne) {
                float u0 = accu[mf][nf][0], u1 = accu[mf][nf][1];
                float h0 = accg[mf][nf][0] * (u0 / (1.f + __expf(-u0)));
                float h1 = accg[mf][nf][1] * (u1 / (1.f + __expf(-u1)));
                *(__half2*)(g_hidh + (size_t)(e * T_TOK + m0 + mrow) * H_DIM + ncol) = __floats2half2_rn(h0, h1);
            }
            if (m0 + mrow + 8 < ne) {
                float u2 = accu[mf][nf][2], u3 = accu[mf][nf][3];
                float h2 = accg[mf][nf][2] * (u2 / (1.f + __expf(-u2)));
                float h3 = accg[mf][nf][3] * (u3 / (1.f + __expf(-u3)));
                *(__half2*)(g_hidh + (size_t)(e * T_TOK + m0 + mrow + 8) * H_DIM + ncol) = __floats2half2_rn(h2, h3);
            }
        }
    }
}

// ---------------- stage B: out[tok[m],:] += w[m] * (hidden[m,:] @ Wd^T[e][n,:]) (R14-proven) ----------------
__global__ void __launch_bounds__(256, 2) ffn2_kernel(float* __restrict__ out) {
    int e = blockIdx.z;
    int ne = g_cnt[e];
    int m0 = blockIdx.x * 128;
    if (m0 >= ne) return;
    int n0 = blockIdx.y * 128;
    extern __shared__ char smem[];
    uint32_t sbase = smem_u32(smem);
    int tid = threadIdx.x, warp = tid >> 5, lane = tid & 31;
    int wm = warp >> 2, wn = warp & 3;
    int ar = lane >> 2, ac = lane & 3;
    int*   toks = (int*)(smem + TOKO2);
    float* wts  = (float*)(smem + WTO2);

    if (tid < 128) {
        int valid = (m0 + tid < ne);
        toks[tid] = valid ? g_tok[e * T_TOK + m0 + tid] : 0;
        wts[tid]  = valid ? g_wt [e * T_TOK + m0 + tid] : 0.f;
    }
    __syncthreads();

    const __half* ag[4]; const __half* bg[4]; uint32_t aso[4];
    #pragma unroll
    for (int j = 0; j < 4; j++) {
        int f = tid + 256 * j, row = f >> 3, c4 = f & 7;
        ag[j] = g_hidh + (size_t)(e * T_TOK + m0 + row) * H_DIM + c4 * 8;
        bg[j] = g_wth + WDT_OFF + (size_t)(e * D_DIM + n0 + row) * H_DIM + c4 * 8;
        aso[j] = row * 144 + c4 * 16;
    }

    auto load_tile = [&](int kc, int buf) {
        uint32_t sa = sbase + ABUF2 + buf * 18432;
        uint32_t sb = sbase + BBUF2 + buf * 18432;
        int ko = kc * 64;
        #pragma unroll
        for (int j = 0; j < 4; j++) {
            CP16(sa + aso[j], ag[j] + ko);
            CP16(sb + aso[j], bg[j] + ko);
        }
        CP_COMMIT();
    };

    float acc[4][4][4];
    #pragma unroll
    for (int i = 0; i < 4; i++)
        #pragma unroll
        for (int j = 0; j < 4; j++)
            #pragma unroll
            for (int k = 0; k < 4; k++) acc[i][j][k] = 0.f;

    load_tile(0, 0);
    const int KT = H_DIM / 64;
    for (int kc = 0; kc < KT; kc++) {
        int cur = kc & 1;
        if (kc + 1 < KT) {
            load_tile(kc + 1, cur ^ 1);
            asm volatile("cp.async.wait_group 1;" ::: "memory");
        } else {
            asm volatile("cp.async.wait_group 0;" ::: "memory");
        }
        __syncthreads();
        const uint32_t* A32 = (const uint32_t*)(smem + ABUF2 + cur * 18432);
        const uint32_t* B32 = (const uint32_t*)(smem + BBUF2 + cur * 18432);
        #pragma unroll
        for (int ks = 0; ks < 4; ks++) {
            uint32_t af[4][4], bf[4][2];
            #pragma unroll
            for (int mf = 0; mf < 4; mf++) {
                int base = (wm * 64 + mf * 16 + ar) * 36 + ks * 8 + ac;
                af[mf][0] = A32[base];       af[mf][1] = A32[base + 288];
                af[mf][2] = A32[base + 4];   af[mf][3] = A32[base + 292];
            }
            #pragma unroll
            for (int nf = 0; nf < 4; nf++) {
                int base = (wn * 32 + nf * 8 + ar) * 36 + ks * 8 + ac;
                bf[nf][0] = B32[base]; bf[nf][1] = B32[base + 4];
            }
            #pragma unroll
            for (int mf = 0; mf < 4; mf++)
                #pragma unroll
                for (int nf = 0; nf < 4; nf++)
                    MMA_F16(acc[mf][nf], af[mf], bf[nf]);
        }
        __syncthreads();
    }

    #pragma unroll
    for (int mf = 0; mf < 4; mf++) {
        int mrow = wm * 64 + mf * 16 + ar;
        #pragma unroll
        for (int nf = 0; nf < 4; nf++) {
            int ncol = n0 + wn * 32 + nf * 8 + 2 * ac;
            if (m0 + mrow < ne) {
                float w = wts[mrow];
                float* dst = out + (size_t)toks[mrow] * D_DIM + ncol;
                atomicAdd(dst,     w * acc[mf][nf][0]);
                atomicAdd(dst + 1, w * acc[mf][nf][1]);
            }
            if (m0 + mrow + 8 < ne) {
                float w = wts[mrow + 8];
                float* dst = out + (size_t)toks[mrow + 8] * D_DIM + ncol;
                atomicAdd(dst,     w * acc[mf][nf][2]);
                atomicAdd(dst + 1, w * acc[mf][nf][3]);
            }
        }
    }
}

// ---------------- aux scalars ----------------
__global__ void finalize_kernel(float* out, int out_size) {
    float aux = 0.f;
    for (int e = 0; e < E_NUM; e++) {
        float imp  = g_imp[e] / 8192.0f;
        float load = (float)g_cnt[e] / (8192.0f + 1e-6f);
        aux += imp * load;
    }
    aux *= (float)E_NUM * 0.01f;
    float ent = g_ent / 8192.0f * 0.01f;
    out[out_size - 3] = aux;
    out[out_size - 2] = ent;
    out[out_size - 1] = 0.f;
}

// ---------------- launch: event-forked side stream for weight prep ----------------
extern "C" void kernel_launch(void* const* d_in, const int* in_sizes, int n_in,
                              void* d_out, int out_size) {
    const float* x    = (const float*)d_in[0];
    const float* rw   = (const float*)d_in[1];
    const float* temp = (const float*)d_in[2];
    const float* Wg   = (const float*)d_in[3];
    const float* Wu   = (const float*)d_in[4];
    const float* Wd   = (const float*)d_in[5];
    float* out = (float*)d_out;

    cudaFuncSetAttribute(ffn1_kernel, cudaFuncAttributeMaxDynamicSharedMemorySize, SMEM1);
    cudaFuncSetAttribute(ffn2_kernel, cudaFuncAttributeMaxDynamicSharedMemorySize, SMEM2);

    cudaStream_t s1;
    cudaEvent_t e0, e1, e2;
    cudaStreamCreateWithFlags(&s1, cudaStreamNonBlocking);
    cudaEventCreateWithFlags(&e0, cudaEventDisableTiming);
    cudaEventCreateWithFlags(&e1, cudaEventDisableTiming);
    cudaEventCreateWithFlags(&e2, cudaEventDisableTiming);

    dim3 tb(32, 8);

    // fork: Wg/Wu transposes on side stream, concurrent with memset+zero+router
    cudaEventRecord(e0, 0);
    cudaStreamWaitEvent(s1, e0, 0);
    transpose_kernel<<<dim3(H_DIM / 32, D_DIM / 32, E_NUM), tb, 0, s1>>>(Wg, WGT_OFF, D_DIM, H_DIM);
    transpose_kernel<<<dim3(H_DIM / 32, D_DIM / 32, E_NUM), tb, 0, s1>>>(Wu, WUT_OFF, D_DIM, H_DIM);
    cudaEventRecord(e1, s1);
    // Wd transpose stays on s1 AFTER e1 -> overlaps ffn1, joins before ffn2
    transpose_kernel<<<dim3(D_DIM / 32, H_DIM / 32, E_NUM), tb, 0, s1>>>(Wd, WDT_OFF, H_DIM, D_DIM);
    cudaEventRecord(e2, s1);

    // main stream: reset + router (also converts x -> fp16)
    cudaMemsetAsync(d_out, 0, (size_t)out_size * sizeof(float));
    zero_kernel<<<1, 32>>>();
    router_kernel<<<T_TOK / 8, 256>>>(x, rw, temp);

    // join Wg/Wu, run ffn1 (Wd transpose overlaps)
    cudaStreamWaitEvent(0, e1, 0);
    ffn1_kernel<<<dim3(64, H_DIM / 128, E_NUM), 256, SMEM1>>>();

    // join Wd, run ffn2
    cudaStreamWaitEvent(0, e2, 0);
    ffn2_kernel<<<dim3(64, D_DIM / 128, E_NUM), 256, SMEM2>>>(out);

    finalize_kernel<<<1, 1>>>(out, out_size);
}